// round 11
// baseline (speedup 1.0000x reference)
#include <cuda_runtime.h>
#include <math.h>

#define BN 4
#define CCH 21
#define HH 96
#define WW 96
#define NN (HH*WW)          // 9216
#define NEH (HH*(WW-1))     // 9120
#define NEV ((HH-1)*WW)     // 9120
#define NE  (NEH+NEV)       // 18240
#define NTREE 8             // s = b*2 + t, t=0 low, t=1 high
#define NCHUNK 32
#define CHSZ  16            // 512 / NCHUNK
#define ROOT  (48*WW + 48)
#define MAXS  5120          // short chains (len<=32)
#define MAXL  640           // long chains (len>32)
#define NLV   17            // chain levels <= log2(NN)+1, padded

// ---------------- scratch ----------------
__device__ double g_ws[NTREE*NE];
__device__ unsigned long long g_key[NTREE*NE];
__device__ double g_part[BN*NCHUNK*NE];
__device__ int    g_adj[NTREE*NN*4];
__device__ int    g_ord[NTREE*NN];     // node at BFS position
__device__ int    g_pp[NTREE*NN];      // parent BFS position
__device__ int    g_cs[NTREE*NN];      // (childcount<<14)|childstart
__device__ int    g_loff[NTREE*(NN+4)];
__device__ int    g_nlev[NTREE];
__device__ float  g_w[NTREE*NN];       // weight, BFS-position indexed
// HLD outputs (chain-order indexed)
__device__ int    g_cnode[NTREE*NN];   // node id at chain position
__device__ float  g_cw2[NTREE*NN];     // parent-edge weight at chain position
__device__ int    g_crecS[NTREE*MAXS]; // (start<<14)|len
__device__ int    g_cparS[NTREE*MAXS]; // chain-pos of head's parent
__device__ int    g_crecL[NTREE*MAXL];
__device__ int    g_cparL[NTREE*MAXL];
__device__ int    g_loffS[NTREE*NLV];
__device__ int    g_loffL[NTREE*NLV];
__device__ int    g_nclv[NTREE];
__device__ float  g_prob[BN*CCH*NN];
__device__ float  g_S[BN*(CCH+1)*NN];
__device__ float  g_S2[BN*(CCH+1)*NN];
__device__ double g_acc[2];

__device__ __forceinline__ void edge_nodes(int e, int &a, int &b) {
    if (e < NEH) { int r = e / (WW-1); int c = e - r*(WW-1); a = r*WW + c; b = a + 1; }
    else         { a = e - NEH; b = a + WW; }
}

__device__ __forceinline__ unsigned long long pack_key(double w, int e) {
    unsigned long long kb = (unsigned long long)__double_as_longlong(w);
    return (kb & ~32767ull) | (unsigned long long)e;
}

__device__ __forceinline__ void two_sum(float a, float b, float &s, float &e) {
    s = __fadd_rn(a, b);
    float bp = __fsub_rn(s, a);
    e = __fadd_rn(__fsub_rn(a, __fsub_rn(s, bp)), __fsub_rn(b, bp));
}

// ---------------- kernels ----------------
__global__ void k_sigmoid(const float* __restrict__ preds) {
    int i = blockIdx.x*blockDim.x + threadIdx.x;
    if (i < 2) g_acc[i] = 0.0;
    if (i < BN*CCH*NN) g_prob[i] = 1.0f/(1.0f + expf(-preds[i]));
}

__global__ void k_ew_high(const float* __restrict__ hf) {
    int idx = blockIdx.x*blockDim.x + threadIdx.x;
    if (idx >= BN*NCHUNK*NE) return;
    int b = idx / (NCHUNK*NE);
    int r = idx - b*(NCHUNK*NE);
    int ch = r / NE, e = r - ch*NE;
    int a, bb; edge_nodes(e, a, bb);
    const float* f = hf + b*512*NN + ch*CHSZ*NN;
    float sh = 0.0f, sl = 0.0f;
    #pragma unroll
    for (int c = 0; c < CHSZ; c++) {
        float av = f[c*NN+a], bv = f[c*NN+bb];
        float dh, dl; two_sum(av, -bv, dh, dl);
        float p  = __fmul_rn(dh, dh);
        float pe = __fmaf_rn(dh, dh, -p);
        pe = __fmaf_rn(__fmul_rn(2.0f, dh), dl, pe);
        float t, er; two_sum(sh, p, t, er);
        sl = __fadd_rn(sl, __fadd_rn(er, pe));
        sh = t;
    }
    g_part[(b*NCHUNK + ch)*NE + e] = (double)sh + (double)sl;
}

__global__ void k_ew_red(const float* __restrict__ lf) {
    int idx = blockIdx.x*blockDim.x + threadIdx.x;
    if (idx >= BN*NE) return;
    int b = idx / NE, e = idx - b*NE;
    int a, bb; edge_nodes(e, a, bb);
    const float* f = lf + b*3*NN;
    double accl = 0.0;
    #pragma unroll
    for (int c = 0; c < 3; c++) {
        double d = (double)f[c*NN+a] - (double)f[c*NN+bb];
        accl += d*d;
    }
    g_ws[(b*2)*NE + e] = accl;
    g_key[(b*2)*NE + e] = pack_key(accl, e);
    double acc = 0.0;
    #pragma unroll 8
    for (int ch = 0; ch < NCHUNK; ch++) acc += g_part[(b*NCHUNK + ch)*NE + e];
    g_ws[(b*2+1)*NE + e] = acc;
    g_key[(b*2+1)*NE + e] = pack_key(acc, e);
}

// Parallel Boruvka, one block per tree.
__global__ void __launch_bounds__(1024) k_boruvka() {
    extern __shared__ unsigned long long sh_u[];
    unsigned long long* minw = sh_u;       // NN
    int* parent = (int*)(minw + NN);       // NN
    int* hook   = parent + NN;             // NN
    int* deg    = hook + NN;               // NN
    __shared__ int total, flag;
    int s = blockIdx.x;
    const unsigned long long* key = g_key + s*NE;
    int* adj = g_adj + s*NN*4;
    for (int i = threadIdx.x; i < NN; i += blockDim.x) { parent[i] = i; deg[i] = 0; }
    for (int i = threadIdx.x; i < NN*4; i += blockDim.x) adj[i] = -1;
    if (threadIdx.x == 0) total = 0;
    __syncthreads();
    for (int round = 0; round < 24; round++) {
        for (int i = threadIdx.x; i < NN; i += blockDim.x) {
            minw[i] = 0xFFFFFFFFFFFFFFFFull; hook[i] = -1;
        }
        __syncthreads();
        for (int e = threadIdx.x; e < NE; e += blockDim.x) {
            int a, b; edge_nodes(e, a, b);
            int ra = parent[a], rb = parent[b];
            if (ra != rb) {
                unsigned long long k = key[e];
                if (k < minw[ra]) atomicMin(&minw[ra], k);
                if (k < minw[rb]) atomicMin(&minw[rb], k);
            }
        }
        __syncthreads();
        for (int i = threadIdx.x; i < NN; i += blockDim.x) {
            unsigned long long mk = minw[i];
            if (parent[i] == i && mk != 0xFFFFFFFFFFFFFFFFull) {
                int e = (int)(mk & 32767ull);
                int a, b; edge_nodes(e, a, b);
                int ra = parent[a], rb = parent[b];
                int other = (ra == i) ? rb : ra;
                bool mutual = (minw[other] == mk);
                if (!mutual || i < other) {
                    int da = atomicAdd(&deg[a], 1); adj[a*4+da] = b;
                    int db = atomicAdd(&deg[b], 1); adj[b*4+db] = a;
                    atomicAdd(&total, 1);
                    hook[i] = other;
                }
            }
        }
        __syncthreads();
        for (int i = threadIdx.x; i < NN; i += blockDim.x) {
            int t = hook[i];
            if (t >= 0) parent[i] = t;
        }
        __syncthreads();
        for (;;) {
            if (threadIdx.x == 0) flag = 0;
            __syncthreads();
            for (int i = threadIdx.x; i < NN; i += blockDim.x) {
                int p = parent[i], gp = parent[p];
                if (p != gp) { parent[i] = gp; flag = 1; }
            }
            __syncthreads();
            int f = flag;
            __syncthreads();
            if (!f) break;
        }
        if (total >= NN-1) break;
    }
}

// Single-warp BFS from ROOT; children sorted by parent (ballot prefix).
__global__ void __launch_bounds__(256) k_bfs() {
    extern __shared__ int sh[];
    int* adj_s = sh;            // NN*4
    int* ord   = adj_s + NN*4;  // NN
    int* pp    = ord + NN;      // NN
    int s = blockIdx.x;
    const int* adj = g_adj + s*NN*4;
    int* loff = g_loff + s*(NN+4);
    for (int i = threadIdx.x; i < NN*4; i += blockDim.x) adj_s[i] = adj[i];
    if (threadIdx.x == 0) { ord[0] = ROOT; pp[0] = 0; loff[0] = 0; loff[1] = 1; }
    __syncthreads();
    if (threadIdx.x < 32) {
        int lane = threadIdx.x;
        unsigned lt = (1u << lane) - 1u;
        int cur = 0, curEnd = 1, lvl = 0;
        for (;;) {
            int total = 0;
            for (int q0 = cur; q0 < curEnd; q0 += 32) {
                int q = q0 + lane;
                int nc = 0; int ch[4];
                if (q < curEnd) {
                    int u = ord[q];
                    int pu = (q == 0) ? -1 : ord[pp[q]];
                    #pragma unroll
                    for (int j = 0; j < 4; j++) {
                        int v = adj_s[u*4 + j];
                        if (v >= 0 && v != pu) ch[nc++] = v;
                    }
                }
                unsigned m0 = __ballot_sync(0xffffffffu, nc > 0);
                unsigned m1 = __ballot_sync(0xffffffffu, nc > 1);
                unsigned m2 = __ballot_sync(0xffffffffu, nc > 2);
                unsigned m3 = __ballot_sync(0xffffffffu, nc > 3);
                int excl = __popc(m0 & lt) + __popc(m1 & lt) + __popc(m2 & lt) + __popc(m3 & lt);
                int base = curEnd + total + excl;
                if (q < curEnd) {
                    for (int i = 0; i < nc; i++) { ord[base+i] = ch[i]; pp[base+i] = q; }
                    g_cs[s*NN + q] = (nc << 14) | base;
                }
                total += __popc(m0) + __popc(m1) + __popc(m2) + __popc(m3);
            }
            __syncwarp();
            if (total == 0) break;
            lvl++;
            if (lane == 0) loff[lvl+1] = curEnd + total;
            cur = curEnd; curEnd += total;
        }
        if (lane == 0) g_nlev[s] = lvl + 1;
    }
    __syncthreads();
    float sig = (s & 1) ? 1.0f : 0.02f;
    for (int k = threadIdx.x; k < NN; k += blockDim.x) {
        g_ord[s*NN + k] = ord[k];
        g_pp[s*NN + k]  = pp[k];
        if (k == 0) { g_w[s*NN] = 0.0f; continue; }
        int v = ord[k];
        int u = ord[pp[k]];
        int e;
        if      (u == v-1)  { int r2 = v/WW, c2 = v%WW; e = r2*(WW-1) + (c2-1); }
        else if (u == v+1)  { int r2 = v/WW, c2 = v%WW; e = r2*(WW-1) + c2; }
        else if (u == v-WW) { e = NEH + (v-WW); }
        else                { e = NEH + v; }
        g_w[s*NN + k] = expf(-(float)g_ws[s*NE + e] / sig);
    }
}

// Heavy-light decomposition, one block per tree. Chains grouped per chain-level
// into SHORT (len<=32) and LONG lists.
__global__ void __launch_bounds__(256) k_hld() {
    extern __shared__ int shi[];
    int* pp    = shi;        // NN
    int* cs    = pp + NN;    // NN
    int* size_ = cs + NN;    // NN (later: len / chain-index stash at heads)
    int* heavy = size_ + NN; // NN (heavy child position, -1 at leaves)
    int* clev  = heavy + NN; // NN
    int* cpos  = clev + NN;  // NN: first BFS loff (aliased), later bfspos->chainpos
    __shared__ int cntS[NLV], cntL[NLV], offS[NLV], offL[NLV], fillS[NLV], fillL[NLV];
    __shared__ int fillNode, maxLv;
    int s = blockIdx.x, tid = threadIdx.x;
    int nl = g_nlev[s];
    int* loffs = cpos;  // alias during level passes
    for (int i = tid; i < NN; i += 256) { pp[i] = g_pp[s*NN+i]; cs[i] = g_cs[s*NN+i]; }
    for (int i = tid; i <= nl; i += 256) loffs[i] = g_loff[s*(NN+4)+i];
    if (tid < NLV) { cntS[tid]=0; cntL[tid]=0; fillS[tid]=0; fillL[tid]=0; }
    if (tid == 0) { fillNode = 0; maxLv = 0; }
    __syncthreads();
    // sizes + heavy child via children-range gather (leaves -> root)
    for (int d = nl-1; d >= 0; --d) {
        int s0 = loffs[d], cnt = loffs[d+1] - s0;
        if (cnt <= 32) {
            if (tid < 32) {
                if (tid < cnt) {
                    int k = s0 + tid;
                    int cp = cs[k], cc = cp >> 14, c0 = cp & 16383;
                    int sz = 1, hv = -1, hsz = 0;
                    for (int i = 0; i < cc; i++) {
                        int sc = size_[c0+i];
                        sz += sc;
                        if (sc > hsz) { hsz = sc; hv = c0+i; }
                    }
                    size_[k] = sz; heavy[k] = hv;
                }
                __syncwarp();
            }
        } else {
            __syncthreads();
            for (int k = s0 + tid; k < s0 + cnt; k += 256) {
                int cp = cs[k], cc = cp >> 14, c0 = cp & 16383;
                int sz = 1, hv = -1, hsz = 0;
                for (int i = 0; i < cc; i++) {
                    int sc = size_[c0+i];
                    sz += sc;
                    if (sc > hsz) { hsz = sc; hv = c0+i; }
                }
                size_[k] = sz; heavy[k] = hv;
            }
            __syncthreads();
        }
    }
    __syncthreads();
    // chain level (root -> leaves)
    if (tid == 0) clev[0] = 0;
    __syncthreads();
    for (int d = 1; d < nl; ++d) {
        int s0 = loffs[d], cnt = loffs[d+1] - s0;
        if (cnt <= 32) {
            if (tid < 32) {
                if (tid < cnt) {
                    int k = s0 + tid, p = pp[k];
                    clev[k] = clev[p] + ((heavy[p] != k) ? 1 : 0);
                }
                __syncwarp();
            }
        } else {
            __syncthreads();
            for (int k = s0 + tid; k < s0 + cnt; k += 256) {
                int p = pp[k];
                clev[k] = clev[p] + ((heavy[p] != k) ? 1 : 0);
            }
            __syncthreads();
        }
    }
    __syncthreads();
    // count chains per level/class; stash len in size_ at heads
    for (int k = tid; k < NN; k += 256) {
        bool head = (k == 0) || (heavy[pp[k]] != k);
        if (head) {
            int len = 1, j = k;
            while (heavy[j] >= 0) { j = heavy[j]; len++; }
            size_[k] = len;
            int lv = clev[k];
            atomicMax(&maxLv, lv);
            if (len <= 32) atomicAdd(&cntS[lv], 1);
            else           atomicAdd(&cntL[lv], 1);
        }
    }
    __syncthreads();
    if (tid == 0) {
        int aS = 0, aL = 0, nlv = maxLv + 1;
        for (int l = 0; l < NLV; ++l) {
            offS[l] = aS; offL[l] = aL;
            if (l < nlv) { aS += cntS[l]; aL += cntL[l]; }
        }
        g_nclv[s] = nlv;
    }
    __syncthreads();
    // place chains: allocate node space, write cnode/cw2, fill cpos map
    for (int k = tid; k < NN; k += 256) {
        bool head = (k == 0) || (heavy[pp[k]] != k);
        if (head) {
            int len = size_[k], lv = clev[k];
            int cs0 = atomicAdd(&fillNode, len);
            int ci, enc;
            if (len <= 32) { ci = offS[lv] + atomicAdd(&fillS[lv], 1); enc = ci; }
            else           { ci = offL[lv] + atomicAdd(&fillL[lv], 1); enc = ci | (1<<30); }
            if (len <= 32) g_crecS[s*MAXS + ci] = (cs0 << 14) | len;
            else           g_crecL[s*MAXL + ci] = (cs0 << 14) | len;
            size_[k] = enc;
            int j = k;
            for (int i = 0; i < len; i++) {
                cpos[j] = cs0 + i;
                g_cnode[s*NN + cs0 + i] = g_ord[s*NN + j];
                g_cw2[s*NN + cs0 + i]   = g_w[s*NN + j];
                j = heavy[j];
                if (j < 0) break;
            }
        }
    }
    __syncthreads();
    // chain parent links
    for (int k = tid; k < NN; k += 256) {
        bool head = (k == 0) || (heavy[pp[k]] != k);
        if (head) {
            int enc = size_[k];
            int parpos = (k == 0) ? 0 : cpos[pp[k]];
            if (enc & (1<<30)) g_cparL[s*MAXL + (enc & 0x3FFFFFFF)] = parpos;
            else               g_cparS[s*MAXS + enc] = parpos;
        }
    }
    __syncthreads();
    if (tid < NLV) { g_loffS[s*NLV + tid] = offS[tid]; g_loffL[s*NLV + tid] = offL[tid]; }
}

// Tree DP via HLD: per chain-level, short chains one-per-THREAD (serial
// register recurrence), long chains one-per-WARP (segmented affine scan).
// <=14 block barriers per pass instead of ~400.
__global__ void __launch_bounds__(256) k_filter(int t, int srcsel, int dst) {
    extern __shared__ float shf[];
    float* val = shf;                 // NN (input -> A')
    float* Ss  = val + NN;            // NN
    float* cw  = Ss + NN;             // NN
    int* cnode = (int*)(cw + NN);     // NN
    int* crecS = cnode + NN;          // MAXS
    int* cparS = crecS + MAXS;        // MAXS
    int* crecL = cparS + MAXS;        // MAXL
    int* cparL = crecL + MAXL;        // MAXL
    __shared__ int loffS[NLV], loffL[NLV], sh_nlv;
    int b = blockIdx.x, c = blockIdx.y;
    int s = b*2 + t;
    int tid = threadIdx.x, wid2 = tid >> 5, lane = tid & 31;
    if (tid == 0) sh_nlv = g_nclv[s];
    if (tid < NLV) { loffS[tid] = g_loffS[s*NLV + tid]; loffL[tid] = g_loffL[s*NLV + tid]; }
    const float* s1c = g_S + (b*(CCH+1) + c)*NN;
    const float* s1n = g_S + (b*(CCH+1) + CCH)*NN;
    for (int i = tid; i < NN; i += 256) {
        int node = g_cnode[s*NN + i];
        cnode[i] = node;
        cw[i]    = g_cw2[s*NN + i];
        float v;
        if (c == CCH)           v = 1.0f;
        else if (srcsel == 0)   v = g_prob[(b*CCH + c)*NN + node];
        else                    v = s1c[node] / s1n[node];
        val[i] = v;
    }
    __syncthreads();
    int nlv = sh_nlv;
    int nS = loffS[nlv], nL = loffL[nlv];
    for (int i = tid; i < nS; i += 256) { crecS[i] = g_crecS[s*MAXS + i]; cparS[i] = g_cparS[s*MAXS + i]; }
    for (int i = tid; i < nL; i += 256) { crecL[i] = g_crecL[s*MAXL + i]; cparL[i] = g_cparL[s*MAXL + i]; }
    __syncthreads();
    // ---- UP: chain-levels deepest -> 0 ----
    for (int L = nlv - 1; L >= 0; --L) {
        // short chains: one per thread
        for (int ci = loffS[L] + tid; ci < loffS[L+1]; ci += 256) {
            int rec = crecS[ci], cs0 = rec >> 14, len = rec & 16383;
            float a = val[cs0 + len - 1];
            for (int j = len - 2; j >= 0; --j) {
                a = __fmaf_rn(cw[cs0+j+1], a, val[cs0+j]);
                val[cs0+j] = a;
            }
            if (cs0 != 0) atomicAdd(&val[cparS[ci]], cw[cs0]*a);
        }
        __syncwarp();
        // long chains: one per warp, reverse segmented affine scan
        for (int ci = loffL[L] + wid2; ci < loffL[L+1]; ci += 8) {
            int rec = crecL[ci], cs0 = rec >> 14, len = rec & 16383;
            int nt = (len + 31) >> 5;
            float carry = 0.f;
            for (int tt = nt - 1; tt >= 0; --tt) {
                int off0 = tt*32 + lane;
                bool valid = off0 < len;
                int j = cs0 + (valid ? off0 : 0);
                float p, q;
                if (valid) { q = val[j]; p = (off0 + 1 < len) ? cw[j+1] : 0.f; }
                else       { q = 0.f; p = 1.f; }
                #pragma unroll
                for (int o = 1; o < 32; o <<= 1) {
                    float P = __shfl_down_sync(0xffffffffu, p, o);
                    float Q = __shfl_down_sync(0xffffffffu, q, o);
                    if (lane + o < 32) { q = __fmaf_rn(p, Q, q); p *= P; }
                }
                float A = __fmaf_rn(p, carry, q);
                if (valid) val[j] = A;
                carry = __shfl_sync(0xffffffffu, A, 0);
            }
            if (lane == 0 && cs0 != 0)
                atomicAdd(&val[cparL[ci]], cw[cs0]*carry);
        }
        __syncthreads();
    }
    // ---- DOWN: chain-levels 0 -> deepest ----
    for (int L = 0; L < nlv; ++L) {
        for (int ci = loffS[L] + tid; ci < loffS[L+1]; ci += 256) {
            int rec = crecS[ci], cs0 = rec >> 14, len = rec & 16383;
            float sp = (cs0 == 0) ? 0.f : Ss[cparS[ci]];
            for (int j = 0; j < len; ++j) {
                float a = val[cs0+j], w = cw[cs0+j];
                sp = __fmaf_rn(w, __fmaf_rn(-w, a, sp), a);
                Ss[cs0+j] = sp;
            }
        }
        __syncwarp();
        for (int ci = loffL[L] + wid2; ci < loffL[L+1]; ci += 8) {
            int rec = crecL[ci], cs0 = rec >> 14, len = rec & 16383;
            int nt = (len + 31) >> 5;
            float carry = (cs0 == 0) ? 0.f : Ss[cparL[ci]];
            for (int tt = 0; tt < nt; ++tt) {
                int off0 = tt*32 + lane;
                bool valid = off0 < len;
                int j = cs0 + (valid ? off0 : 0);
                float p, q;
                if (valid) {
                    float a = cw[j], f = val[j];
                    p = a;
                    q = f - a*a*f;
                } else { p = 1.f; q = 0.f; }
                #pragma unroll
                for (int o = 1; o < 32; o <<= 1) {
                    float P = __shfl_up_sync(0xffffffffu, p, o);
                    float Q = __shfl_up_sync(0xffffffffu, q, o);
                    if (lane >= o) { q = __fmaf_rn(p, Q, q); p *= P; }
                }
                float Sv = __fmaf_rn(p, carry, q);
                if (valid) Ss[j] = Sv;
                carry = __shfl_sync(0xffffffffu, Sv, 31);
            }
        }
        __syncthreads();
    }
    float* outS = ((dst == 0) ? g_S : g_S2) + (b*(CCH+1) + c)*NN;
    for (int i = tid; i < NN; i += 256) outS[cnode[i]] = Ss[i];
}

__global__ void k_loss(const float* __restrict__ roi) {
    __shared__ double sl[256], sn[256];
    int idx = blockIdx.x*blockDim.x + threadIdx.x;
    double l = 0.0, n = 0.0;
    if (idx < BN*NN) {
        int b = idx / NN, i = idx - b*NN;
        int h = i / WW, w = i - h*WW;
        float r = roi[b*(2*HH)*(2*WW) + (2*h)*(2*WW) + 2*w];
        n = (double)r;
        if (r != 0.0f) {
            float nrm = g_S2[(b*(CCH+1) + CCH)*NN + i];
            double acc = 0.0;
            for (int c = 0; c < CCH; c++) {
                float as = g_S2[(b*(CCH+1) + c)*NN + i] / nrm;
                acc += (double)fabsf(g_prob[(b*CCH + c)*NN + i] - as);
            }
            l = acc * (double)r;
        }
    }
    sl[threadIdx.x] = l; sn[threadIdx.x] = n;
    __syncthreads();
    for (int o = 128; o; o >>= 1) {
        if (threadIdx.x < o) { sl[threadIdx.x] += sl[threadIdx.x+o]; sn[threadIdx.x] += sn[threadIdx.x+o]; }
        __syncthreads();
    }
    if (threadIdx.x == 0) { atomicAdd(&g_acc[0], sl[0]); atomicAdd(&g_acc[1], sn[0]); }
}

__global__ void k_fin(float* out) {
    if (threadIdx.x == 0)
        out[0] = (g_acc[1] > 0.0) ? (float)(g_acc[0]/g_acc[1]) : 0.0f;
}

// ---------------- launch ----------------
extern "C" void kernel_launch(void* const* d_in, const int* in_sizes, int n_in,
                              void* d_out, int out_size) {
    const float* preds = (const float*)d_in[0];
    const float* lf    = (const float*)d_in[1];
    const float* hf    = (const float*)d_in[2];
    const float* roi   = (const float*)d_in[3];
    float* out = (float*)d_out;

    const int smem_boruvka = NN*8 + 3*NN*4;                   // 184320
    const int smem_bfs     = 6*NN*4;                          // 221184
    const int smem_hld     = 6*NN*4;                          // 221184
    const int smem_filter  = 4*NN*4 + 2*MAXS*4 + 2*MAXL*4;    // 193536
    cudaFuncSetAttribute(k_boruvka, cudaFuncAttributeMaxDynamicSharedMemorySize, smem_boruvka);
    cudaFuncSetAttribute(k_bfs,     cudaFuncAttributeMaxDynamicSharedMemorySize, smem_bfs);
    cudaFuncSetAttribute(k_hld,     cudaFuncAttributeMaxDynamicSharedMemorySize, smem_hld);
    cudaFuncSetAttribute(k_filter,  cudaFuncAttributeMaxDynamicSharedMemorySize, smem_filter);

    k_sigmoid<<<(BN*CCH*NN + 255)/256, 256>>>(preds);
    k_ew_high<<<(BN*NCHUNK*NE + 255)/256, 256>>>(hf);
    k_ew_red <<<(BN*NE + 255)/256, 256>>>(lf);
    k_boruvka<<<NTREE, 1024, smem_boruvka>>>();
    k_bfs    <<<NTREE, 256, smem_bfs>>>();
    k_hld    <<<NTREE, 256, smem_hld>>>();
    {
        dim3 g1(BN, CCH+1);
        k_filter<<<g1, 256, smem_filter>>>(0, 0, 0);
        k_filter<<<g1, 256, smem_filter>>>(1, 1, 1);
    }
    k_loss   <<<(BN*NN + 255)/256, 256>>>(roi);
    k_fin    <<<1, 32>>>(out);
}

// round 12
// speedup vs baseline: 1.0739x; 1.0739x over previous
#include <cuda_runtime.h>
#include <math.h>

#define BN 4
#define CCH 21
#define HH 96
#define WW 96
#define NN (HH*WW)          // 9216
#define NEH (HH*(WW-1))     // 9120
#define NEV ((HH-1)*WW)     // 9120
#define NE  (NEH+NEV)       // 18240
#define NTREE 8             // s = b*2 + t, t=0 low, t=1 high
#define NCHUNK 32
#define CHSZ  16            // 512 / NCHUNK
#define ROOT  (48*WW + 48)

// ---------------- scratch ----------------
__device__ double g_ws[NTREE*NE];
__device__ unsigned long long g_key[NTREE*NE];
__device__ double g_part[BN*NCHUNK*NE];
__device__ int    g_adj[NTREE*NN*4];
__device__ int    g_ord[NTREE*NN];     // node at BFS position
__device__ int    g_pp[NTREE*NN];      // parent BFS position
__device__ int    g_cs[NTREE*NN];      // (childcount<<14)|childstart
__device__ int    g_loff[NTREE*(NN+4)];
__device__ int    g_nlev[NTREE];
__device__ float  g_w[NTREE*NN];       // weight, BFS-position indexed
__device__ float  g_prob[BN*CCH*NN];
__device__ float  g_S[BN*(CCH+1)*NN];
__device__ float  g_S2[BN*(CCH+1)*NN];
__device__ double g_acc[2];

__device__ __forceinline__ void edge_nodes(int e, int &a, int &b) {
    if (e < NEH) { int r = e / (WW-1); int c = e - r*(WW-1); a = r*WW + c; b = a + 1; }
    else         { a = e - NEH; b = a + WW; }
}

__device__ __forceinline__ unsigned long long pack_key(double w, int e) {
    unsigned long long kb = (unsigned long long)__double_as_longlong(w);
    return (kb & ~32767ull) | (unsigned long long)e;
}

__device__ __forceinline__ void two_sum(float a, float b, float &s, float &e) {
    s = __fadd_rn(a, b);
    float bp = __fsub_rn(s, a);
    e = __fadd_rn(__fsub_rn(a, __fsub_rn(s, bp)), __fsub_rn(b, bp));
}

// ---------------- kernels ----------------
__global__ void k_sigmoid(const float* __restrict__ preds) {
    int i = blockIdx.x*blockDim.x + threadIdx.x;
    if (i < 2) g_acc[i] = 0.0;
    if (i < BN*CCH*NN) g_prob[i] = 1.0f/(1.0f + expf(-preds[i]));
}

__global__ void k_ew_high(const float* __restrict__ hf) {
    int idx = blockIdx.x*blockDim.x + threadIdx.x;
    if (idx >= BN*NCHUNK*NE) return;
    int b = idx / (NCHUNK*NE);
    int r = idx - b*(NCHUNK*NE);
    int ch = r / NE, e = r - ch*NE;
    int a, bb; edge_nodes(e, a, bb);
    const float* f = hf + b*512*NN + ch*CHSZ*NN;
    float sh = 0.0f, sl = 0.0f;
    #pragma unroll
    for (int c = 0; c < CHSZ; c++) {
        float av = f[c*NN+a], bv = f[c*NN+bb];
        float dh, dl; two_sum(av, -bv, dh, dl);
        float p  = __fmul_rn(dh, dh);
        float pe = __fmaf_rn(dh, dh, -p);
        pe = __fmaf_rn(__fmul_rn(2.0f, dh), dl, pe);
        float t, er; two_sum(sh, p, t, er);
        sl = __fadd_rn(sl, __fadd_rn(er, pe));
        sh = t;
    }
    g_part[(b*NCHUNK + ch)*NE + e] = (double)sh + (double)sl;
}

__global__ void k_ew_red(const float* __restrict__ lf) {
    int idx = blockIdx.x*blockDim.x + threadIdx.x;
    if (idx >= BN*NE) return;
    int b = idx / NE, e = idx - b*NE;
    int a, bb; edge_nodes(e, a, bb);
    const float* f = lf + b*3*NN;
    double accl = 0.0;
    #pragma unroll
    for (int c = 0; c < 3; c++) {
        double d = (double)f[c*NN+a] - (double)f[c*NN+bb];
        accl += d*d;
    }
    g_ws[(b*2)*NE + e] = accl;
    g_key[(b*2)*NE + e] = pack_key(accl, e);
    double acc = 0.0;
    #pragma unroll 8
    for (int ch = 0; ch < NCHUNK; ch++) acc += g_part[(b*NCHUNK + ch)*NE + e];
    g_ws[(b*2+1)*NE + e] = acc;
    g_key[(b*2+1)*NE + e] = pack_key(acc, e);
}

// Parallel Boruvka, one block per tree.
__global__ void __launch_bounds__(1024) k_boruvka() {
    extern __shared__ unsigned long long sh_u[];
    unsigned long long* minw = sh_u;       // NN
    int* parent = (int*)(minw + NN);       // NN
    int* hook   = parent + NN;             // NN
    int* deg    = hook + NN;               // NN
    __shared__ int total, flag;
    int s = blockIdx.x;
    const unsigned long long* key = g_key + s*NE;
    int* adj = g_adj + s*NN*4;
    for (int i = threadIdx.x; i < NN; i += blockDim.x) { parent[i] = i; deg[i] = 0; }
    for (int i = threadIdx.x; i < NN*4; i += blockDim.x) adj[i] = -1;
    if (threadIdx.x == 0) total = 0;
    __syncthreads();
    for (int round = 0; round < 24; round++) {
        for (int i = threadIdx.x; i < NN; i += blockDim.x) {
            minw[i] = 0xFFFFFFFFFFFFFFFFull; hook[i] = -1;
        }
        __syncthreads();
        for (int e = threadIdx.x; e < NE; e += blockDim.x) {
            int a, b; edge_nodes(e, a, b);
            int ra = parent[a], rb = parent[b];
            if (ra != rb) {
                unsigned long long k = key[e];
                if (k < minw[ra]) atomicMin(&minw[ra], k);
                if (k < minw[rb]) atomicMin(&minw[rb], k);
            }
        }
        __syncthreads();
        for (int i = threadIdx.x; i < NN; i += blockDim.x) {
            unsigned long long mk = minw[i];
            if (parent[i] == i && mk != 0xFFFFFFFFFFFFFFFFull) {
                int e = (int)(mk & 32767ull);
                int a, b; edge_nodes(e, a, b);
                int ra = parent[a], rb = parent[b];
                int other = (ra == i) ? rb : ra;
                bool mutual = (minw[other] == mk);
                if (!mutual || i < other) {
                    int da = atomicAdd(&deg[a], 1); adj[a*4+da] = b;
                    int db = atomicAdd(&deg[b], 1); adj[b*4+db] = a;
                    atomicAdd(&total, 1);
                    hook[i] = other;
                }
            }
        }
        __syncthreads();
        for (int i = threadIdx.x; i < NN; i += blockDim.x) {
            int t = hook[i];
            if (t >= 0) parent[i] = t;
        }
        __syncthreads();
        for (;;) {
            if (threadIdx.x == 0) flag = 0;
            __syncthreads();
            for (int i = threadIdx.x; i < NN; i += blockDim.x) {
                int p = parent[i], gp = parent[p];
                if (p != gp) { parent[i] = gp; flag = 1; }
            }
            __syncthreads();
            int f = flag;
            __syncthreads();
            if (!f) break;
        }
        if (total >= NN-1) break;
    }
}

// Single-warp BFS from ROOT; children sorted by parent (ballot prefix).
__global__ void __launch_bounds__(256) k_bfs() {
    extern __shared__ int sh[];
    int* adj_s = sh;            // NN*4
    int* ord   = adj_s + NN*4;  // NN
    int* pp    = ord + NN;      // NN
    int s = blockIdx.x;
    const int* adj = g_adj + s*NN*4;
    int* loff = g_loff + s*(NN+4);
    for (int i = threadIdx.x; i < NN*4; i += blockDim.x) adj_s[i] = adj[i];
    if (threadIdx.x == 0) { ord[0] = ROOT; pp[0] = 0; loff[0] = 0; loff[1] = 1; }
    __syncthreads();
    if (threadIdx.x < 32) {
        int lane = threadIdx.x;
        unsigned lt = (1u << lane) - 1u;
        int cur = 0, curEnd = 1, lvl = 0;
        for (;;) {
            int total = 0;
            for (int q0 = cur; q0 < curEnd; q0 += 32) {
                int q = q0 + lane;
                int nc = 0; int ch[4];
                if (q < curEnd) {
                    int u = ord[q];
                    int pu = (q == 0) ? -1 : ord[pp[q]];
                    #pragma unroll
                    for (int j = 0; j < 4; j++) {
                        int v = adj_s[u*4 + j];
                        if (v >= 0 && v != pu) ch[nc++] = v;
                    }
                }
                unsigned m0 = __ballot_sync(0xffffffffu, nc > 0);
                unsigned m1 = __ballot_sync(0xffffffffu, nc > 1);
                unsigned m2 = __ballot_sync(0xffffffffu, nc > 2);
                unsigned m3 = __ballot_sync(0xffffffffu, nc > 3);
                int excl = __popc(m0 & lt) + __popc(m1 & lt) + __popc(m2 & lt) + __popc(m3 & lt);
                int base = curEnd + total + excl;
                if (q < curEnd) {
                    for (int i = 0; i < nc; i++) { ord[base+i] = ch[i]; pp[base+i] = q; }
                    g_cs[s*NN + q] = (nc << 14) | base;
                }
                total += __popc(m0) + __popc(m1) + __popc(m2) + __popc(m3);
            }
            __syncwarp();
            if (total == 0) break;
            lvl++;
            if (lane == 0) loff[lvl+1] = curEnd + total;
            cur = curEnd; curEnd += total;
        }
        if (lane == 0) g_nlev[s] = lvl + 1;
    }
    __syncthreads();
    float sig = (s & 1) ? 1.0f : 0.02f;
    for (int k = threadIdx.x; k < NN; k += blockDim.x) {
        g_ord[s*NN + k] = ord[k];
        g_pp[s*NN + k]  = pp[k];
        if (k == 0) { g_w[s*NN] = 0.0f; continue; }
        int v = ord[k];
        int u = ord[pp[k]];
        int e;
        if      (u == v-1)  { int r2 = v/WW, c2 = v%WW; e = r2*(WW-1) + (c2-1); }
        else if (u == v+1)  { int r2 = v/WW, c2 = v%WW; e = r2*(WW-1) + c2; }
        else if (u == v-WW) { e = NEH + (v-WW); }
        else                { e = NEH + v; }
        g_w[s*NN + k] = expf(-(float)g_ws[s*NE + e] / sig);
    }
}

// Two-pass tree DP, one block per (batch, channel). Warp path packs multiple
// consecutive small levels into one 32-lane group: one set of parallel loads,
// then a short cascade of register shuffles per level — no barriers at all.
// Big levels (>32) use block-wide gather/scatter-free passes.
// smem S (down) aliases csp (up).
__global__ void __launch_bounds__(256) k_filter(int t, int srcsel, int dst) {
    extern __shared__ float shf[];
    float* A = shf;                 // NN (input -> A')
    float* w = A + NN;              // NN
    int* pp    = (int*)(w + NN);    // NN
    int* SCU   = pp + NN;           // NN: csp during up, S during down
    int* loffs = SCU + NN;          // NN+4
    int* csp = SCU;
    float* S = (float*)SCU;
    int b = blockIdx.x, c = blockIdx.y;
    int s = b*2 + t;
    int nl = g_nlev[s];
    const float* s1c = g_S + (b*(CCH+1) + c)*NN;
    const float* s1n = g_S + (b*(CCH+1) + CCH)*NN;
    const int* ordg = g_ord + s*NN;
    for (int i = threadIdx.x; i < NN; i += 256) {
        int node = ordg[i];
        float v;
        if (c == CCH)           v = 1.0f;
        else if (srcsel == 0)   v = g_prob[(b*CCH + c)*NN + node];
        else                    v = s1c[node] / s1n[node];
        A[i]   = v;
        w[i]   = g_w[s*NN + i];
        csp[i] = g_cs[s*NN + i];
    }
    for (int i = threadIdx.x; i <= nl; i += 256) loffs[i] = g_loff[s*(NN+4) + i];
    __syncthreads();
    int tid = threadIdx.x, lane = tid & 31;
    const unsigned FULL = 0xffffffffu;
    // ================= UP: leaves -> root =================
    {
        bool regv = false; int prevBase = 0;
        float Areg = 0.f;
        int d = nl - 1;
        while (d >= 0) {
            int cnt = loffs[d+1] - loffs[d];
            if (cnt > 32) {
                __syncthreads();
                for (int k = loffs[d] + tid; k < loffs[d+1]; k += 256) {
                    int cp = csp[k], cc = cp >> 14, cs = cp & 16383;
                    float a = A[k];
                    for (int i = 0; i < cc; i++) a = __fmaf_rn(w[cs+i], A[cs+i], a);
                    A[k] = a;
                }
                __syncthreads();
                regv = false;
                d--;
                continue;
            }
            // group levels [dTop, dStart] with total <= 32
            int dStart = d, dTop = d;
            while (dTop > 0) {
                int pc = loffs[dTop] - loffs[dTop-1];
                if (pc > 32) break;
                if (loffs[dStart+1] - loffs[dTop-1] > 32) break;
                dTop--;
            }
            int base = loffs[dTop];
            int gcnt = loffs[dStart+1] - base;
            if (tid < 32) {
                bool valid = lane < gcnt;
                int k = base + (valid ? lane : 0);
                int cp = csp[k];
                int cc = valid ? (cp >> 14) : 0;
                int cs = cp & 16383;
                float a = A[k];
                float wc0 = w[(cs+0 < NN) ? cs+0 : 0];
                float wc1 = w[(cs+1 < NN) ? cs+1 : 0];
                float wc2 = w[(cs+2 < NN) ? cs+2 : 0];
                float wc3 = w[(cs+3 < NN) ? cs+3 : 0];
                float Anew = a;
                for (int dd = dStart; dd >= dTop; dd--) {
                    bool act = valid && (k >= loffs[dd]) && (k < loffs[dd+1]);
                    float c0, c1, c2, c3;
                    if (dd == dStart) {
                        if (regv) {
                            c0 = __shfl_sync(FULL, Areg, (cs+0-prevBase) & 31);
                            c1 = __shfl_sync(FULL, Areg, (cs+1-prevBase) & 31);
                            c2 = __shfl_sync(FULL, Areg, (cs+2-prevBase) & 31);
                            c3 = __shfl_sync(FULL, Areg, (cs+3-prevBase) & 31);
                        } else {
                            c0 = A[(cs+0 < NN) ? cs+0 : 0];
                            c1 = A[(cs+1 < NN) ? cs+1 : 0];
                            c2 = A[(cs+2 < NN) ? cs+2 : 0];
                            c3 = A[(cs+3 < NN) ? cs+3 : 0];
                        }
                    } else {
                        c0 = __shfl_sync(FULL, Anew, (cs+0-base) & 31);
                        c1 = __shfl_sync(FULL, Anew, (cs+1-base) & 31);
                        c2 = __shfl_sync(FULL, Anew, (cs+2-base) & 31);
                        c3 = __shfl_sync(FULL, Anew, (cs+3-base) & 31);
                    }
                    if (act) {
                        if (cc > 0) Anew = __fmaf_rn(wc0, c0, Anew);
                        if (cc > 1) Anew = __fmaf_rn(wc1, c1, Anew);
                        if (cc > 2) Anew = __fmaf_rn(wc2, c2, Anew);
                        if (cc > 3) Anew = __fmaf_rn(wc3, c3, Anew);
                    }
                }
                if (valid) A[k] = Anew;
                Areg = Anew;
            }
            prevBase = base;
            regv = true;
            d = dTop - 1;
        }
    }
    __syncthreads();
    // load pp now (down pass needs it; csp region becomes S)
    for (int i = tid; i < NN; i += 256) pp[i] = g_pp[s*NN + i];
    if (tid == 0) S[0] = A[0];    // root: S = A'
    __syncthreads();
    // ================= DOWN: root -> leaves =================
    {
        bool regv = false; int prevBase = 0;
        float Sreg = 0.f;
        int d = 1;
        while (d < nl) {
            int s0 = loffs[d];
            int cnt = loffs[d+1] - s0;
            if (cnt > 32) {
                __syncthreads();
                for (int k = s0 + tid; k < s0 + cnt; k += 256) {
                    float a = A[k], wv = w[k];
                    S[k] = __fmaf_rn(wv, __fmaf_rn(-wv, a, S[pp[k]]), a);
                }
                __syncthreads();
                regv = false;
                d++;
                continue;
            }
            int dEnd = d + 1;
            while (dEnd < nl && loffs[dEnd+1] - s0 <= 32) dEnd++;
            int gcnt = loffs[dEnd] - s0;
            if (tid < 32) {
                bool valid = lane < gcnt;
                int k = s0 + (valid ? lane : 0);
                int pk = pp[k];
                float a = A[k], wv = w[k];
                float Snew = 0.f;
                // stage 0: level d (parent outside group)
                {
                    float Sp;
                    if (regv) Sp = __shfl_sync(FULL, Sreg, (pk - prevBase) & 31);
                    else      Sp = S[pk];
                    bool act = valid && (k < loffs[d+1]);
                    if (act) Snew = __fmaf_rn(wv, __fmaf_rn(-wv, a, Sp), a);
                }
                for (int dd = d + 1; dd < dEnd; dd++) {
                    float Sp = __shfl_sync(FULL, Snew, (pk - s0) & 31);
                    bool act = valid && (k >= loffs[dd]) && (k < loffs[dd+1]);
                    if (act) Snew = __fmaf_rn(wv, __fmaf_rn(-wv, a, Sp), a);
                }
                if (valid) S[k] = Snew;
                Sreg = Snew;
            }
            prevBase = s0;
            regv = true;
            d = dEnd;
        }
    }
    __syncthreads();
    float* outS = ((dst == 0) ? g_S : g_S2) + (b*(CCH+1) + c)*NN;
    for (int i = tid; i < NN; i += 256) outS[ordg[i]] = S[i];
}

__global__ void k_loss(const float* __restrict__ roi) {
    __shared__ double sl[256], sn[256];
    int idx = blockIdx.x*blockDim.x + threadIdx.x;
    double l = 0.0, n = 0.0;
    if (idx < BN*NN) {
        int b = idx / NN, i = idx - b*NN;
        int h = i / WW, w = i - h*WW;
        float r = roi[b*(2*HH)*(2*WW) + (2*h)*(2*WW) + 2*w];
        n = (double)r;
        if (r != 0.0f) {
            float nrm = g_S2[(b*(CCH+1) + CCH)*NN + i];
            double acc = 0.0;
            for (int c = 0; c < CCH; c++) {
                float as = g_S2[(b*(CCH+1) + c)*NN + i] / nrm;
                acc += (double)fabsf(g_prob[(b*CCH + c)*NN + i] - as);
            }
            l = acc * (double)r;
        }
    }
    sl[threadIdx.x] = l; sn[threadIdx.x] = n;
    __syncthreads();
    for (int o = 128; o; o >>= 1) {
        if (threadIdx.x < o) { sl[threadIdx.x] += sl[threadIdx.x+o]; sn[threadIdx.x] += sn[threadIdx.x+o]; }
        __syncthreads();
    }
    if (threadIdx.x == 0) { atomicAdd(&g_acc[0], sl[0]); atomicAdd(&g_acc[1], sn[0]); }
}

__global__ void k_fin(float* out) {
    if (threadIdx.x == 0)
        out[0] = (g_acc[1] > 0.0) ? (float)(g_acc[0]/g_acc[1]) : 0.0f;
}

// ---------------- launch ----------------
extern "C" void kernel_launch(void* const* d_in, const int* in_sizes, int n_in,
                              void* d_out, int out_size) {
    const float* preds = (const float*)d_in[0];
    const float* lf    = (const float*)d_in[1];
    const float* hf    = (const float*)d_in[2];
    const float* roi   = (const float*)d_in[3];
    float* out = (float*)d_out;

    const int smem_boruvka = NN*8 + 3*NN*4;          // 184320
    const int smem_bfs     = 6*NN*4;                 // 221184
    const int smem_filter  = 4*NN*4 + (NN+4)*4;      // 184336
    cudaFuncSetAttribute(k_boruvka, cudaFuncAttributeMaxDynamicSharedMemorySize, smem_boruvka);
    cudaFuncSetAttribute(k_bfs,     cudaFuncAttributeMaxDynamicSharedMemorySize, smem_bfs);
    cudaFuncSetAttribute(k_filter,  cudaFuncAttributeMaxDynamicSharedMemorySize, smem_filter);

    k_sigmoid<<<(BN*CCH*NN + 255)/256, 256>>>(preds);
    k_ew_high<<<(BN*NCHUNK*NE + 255)/256, 256>>>(hf);
    k_ew_red <<<(BN*NE + 255)/256, 256>>>(lf);
    k_boruvka<<<NTREE, 1024, smem_boruvka>>>();
    k_bfs    <<<NTREE, 256, smem_bfs>>>();
    {
        dim3 g1(BN, CCH+1);
        k_filter<<<g1, 256, smem_filter>>>(0, 0, 0);
        k_filter<<<g1, 256, smem_filter>>>(1, 1, 1);
    }
    k_loss   <<<(BN*NN + 255)/256, 256>>>(roi);
    k_fin    <<<1, 32>>>(out);
}

// round 13
// speedup vs baseline: 1.2498x; 1.1638x over previous
#include <cuda_runtime.h>
#include <math.h>

#define BN 4
#define CCH 21
#define HH 96
#define WW 96
#define NN (HH*WW)          // 9216
#define NEH (HH*(WW-1))     // 9120
#define NEV ((HH-1)*WW)     // 9120
#define NE  (NEH+NEV)       // 18240
#define NTREE 8             // s = b*2 + t, t=0 low, t=1 high
#define NCHUNK 32
#define CHSZ  16            // 512 / NCHUNK
#define ROOT  (48*WW + 48)  // center root (two-pass filter is root-invariant)

// ---------------- scratch ----------------
__device__ double g_ws[NTREE*NE];
__device__ unsigned long long g_key[NTREE*NE];
__device__ double g_part[BN*NCHUNK*NE];
__device__ int    g_adj[NTREE*NN*4];
__device__ int    g_ord[NTREE*NN];     // node at BFS position
__device__ int    g_pp[NTREE*NN];      // parent BFS position
__device__ int    g_loff[NTREE*(NN+4)];
__device__ int    g_nlev[NTREE];
__device__ float  g_w[NTREE*NN];       // weight, BFS-position indexed
__device__ float  g_S[BN*(CCH+1)*NN];
__device__ float  g_S2[BN*(CCH+1)*NN];
__device__ double g_acc[2];

__device__ __forceinline__ void edge_nodes(int e, int &a, int &b) {
    if (e < NEH) { int r = e / (WW-1); int c = e - r*(WW-1); a = r*WW + c; b = a + 1; }
    else         { a = e - NEH; b = a + WW; }
}

__device__ __forceinline__ unsigned long long pack_key(double w, int e) {
    unsigned long long kb = (unsigned long long)__double_as_longlong(w);
    return (kb & ~32767ull) | (unsigned long long)e;
}

__device__ __forceinline__ void two_sum(float a, float b, float &s, float &e) {
    s = __fadd_rn(a, b);
    float bp = __fsub_rn(s, a);
    e = __fadd_rn(__fsub_rn(a, __fsub_rn(s, bp)), __fsub_rn(b, bp));
}

// ---------------- kernels ----------------
__global__ void k_ew_high(const float* __restrict__ hf) {
    int idx = blockIdx.x*blockDim.x + threadIdx.x;
    if (idx >= BN*NCHUNK*NE) return;
    int b = idx / (NCHUNK*NE);
    int r = idx - b*(NCHUNK*NE);
    int ch = r / NE, e = r - ch*NE;
    int a, bb; edge_nodes(e, a, bb);
    const float* f = hf + b*512*NN + ch*CHSZ*NN;
    float sh = 0.0f, sl = 0.0f;
    #pragma unroll
    for (int c = 0; c < CHSZ; c++) {
        float av = f[c*NN+a], bv = f[c*NN+bb];
        float dh, dl; two_sum(av, -bv, dh, dl);
        float p  = __fmul_rn(dh, dh);
        float pe = __fmaf_rn(dh, dh, -p);
        pe = __fmaf_rn(__fmul_rn(2.0f, dh), dl, pe);
        float t, er; two_sum(sh, p, t, er);
        sl = __fadd_rn(sl, __fadd_rn(er, pe));
        sh = t;
    }
    g_part[(b*NCHUNK + ch)*NE + e] = (double)sh + (double)sl;
}

__global__ void k_ew_red(const float* __restrict__ lf) {
    int idx = blockIdx.x*blockDim.x + threadIdx.x;
    if (idx < 2) g_acc[idx] = 0.0;
    if (idx >= BN*NE) return;
    int b = idx / NE, e = idx - b*NE;
    int a, bb; edge_nodes(e, a, bb);
    const float* f = lf + b*3*NN;
    double accl = 0.0;
    #pragma unroll
    for (int c = 0; c < 3; c++) {
        double d = (double)f[c*NN+a] - (double)f[c*NN+bb];
        accl += d*d;
    }
    g_ws[(b*2)*NE + e] = accl;
    g_key[(b*2)*NE + e] = pack_key(accl, e);
    double acc = 0.0;
    #pragma unroll 8
    for (int ch = 0; ch < NCHUNK; ch++) acc += g_part[(b*NCHUNK + ch)*NE + e];
    g_ws[(b*2+1)*NE + e] = acc;
    g_key[(b*2+1)*NE + e] = pack_key(acc, e);
}

// Fused MST (parallel Boruvka) + BFS + weights, one block per tree.
__global__ void __launch_bounds__(1024) k_mstbfs() {
    extern __shared__ char smraw[];
    int s = blockIdx.x;
    int tid = threadIdx.x;
    // ---------- phase 1: Boruvka ----------
    {
        unsigned long long* minw = (unsigned long long*)smraw;   // NN
        int* parent = (int*)(minw + NN);                         // NN
        int* hook   = parent + NN;                               // NN
        int* deg    = hook + NN;                                 // NN
        __shared__ int total, flag;
        const unsigned long long* key = g_key + s*NE;
        int* adj = g_adj + s*NN*4;
        for (int i = tid; i < NN; i += 1024) { parent[i] = i; deg[i] = 0; }
        for (int i = tid; i < NN*4; i += 1024) adj[i] = -1;
        if (tid == 0) total = 0;
        __syncthreads();
        for (int round = 0; round < 24; round++) {
            for (int i = tid; i < NN; i += 1024) {
                minw[i] = 0xFFFFFFFFFFFFFFFFull; hook[i] = -1;
            }
            __syncthreads();
            for (int e = tid; e < NE; e += 1024) {
                int a, b; edge_nodes(e, a, b);
                int ra = parent[a], rb = parent[b];
                if (ra != rb) {
                    unsigned long long k = key[e];
                    if (k < minw[ra]) atomicMin(&minw[ra], k);
                    if (k < minw[rb]) atomicMin(&minw[rb], k);
                }
            }
            __syncthreads();
            for (int i = tid; i < NN; i += 1024) {
                unsigned long long mk = minw[i];
                if (parent[i] == i && mk != 0xFFFFFFFFFFFFFFFFull) {
                    int e = (int)(mk & 32767ull);
                    int a, b; edge_nodes(e, a, b);
                    int ra = parent[a], rb = parent[b];
                    int other = (ra == i) ? rb : ra;
                    bool mutual = (minw[other] == mk);
                    if (!mutual || i < other) {
                        int da = atomicAdd(&deg[a], 1); adj[a*4+da] = b;
                        int db = atomicAdd(&deg[b], 1); adj[b*4+db] = a;
                        atomicAdd(&total, 1);
                        hook[i] = other;
                    }
                }
            }
            __syncthreads();
            for (int i = tid; i < NN; i += 1024) {
                int t = hook[i];
                if (t >= 0) parent[i] = t;
            }
            __syncthreads();
            for (;;) {
                if (tid == 0) flag = 0;
                __syncthreads();
                for (int i = tid; i < NN; i += 1024) {
                    int p = parent[i], gp = parent[p];
                    if (p != gp) { parent[i] = gp; flag = 1; }
                }
                __syncthreads();
                int f = flag;
                __syncthreads();
                if (!f) break;
            }
            if (total >= NN-1) break;
        }
    }
    __syncthreads();
    // ---------- phase 2: single-warp BFS + weights ----------
    {
        int* adj_s = (int*)smraw;   // NN*4
        int* ord   = adj_s + NN*4;  // NN
        int* pp    = ord + NN;      // NN
        int* cnts  = pp + NN;       // 64 rotating counters
        const int* adj = g_adj + s*NN*4;
        int* loff = g_loff + s*(NN+4);
        for (int i = tid; i < NN*4; i += 1024) adj_s[i] = adj[i];
        for (int i = tid; i < 64; i += 1024) cnts[i] = 0;
        if (tid == 0) { ord[0] = ROOT; pp[0] = 0; loff[0] = 0; loff[1] = 1; }
        __syncthreads();
        if (tid < 32) {
            int lane = tid;
            int cur = 0, curEnd = 1, lvl = 0;
            for (;;) {
                int slot = lvl & 63;
                for (int q = cur + lane; q < curEnd; q += 32) {
                    int u = ord[q];
                    int pu = (q == 0) ? -1 : ord[pp[q]];
                    #pragma unroll
                    for (int j = 0; j < 4; j++) {
                        int v = adj_s[u*4 + j];
                        if (v >= 0 && v != pu) {
                            int pos = atomicAdd(&cnts[slot], 1);
                            ord[curEnd + pos] = v;
                            pp[curEnd + pos] = q;
                        }
                    }
                }
                __syncwarp();
                int c = cnts[slot];
                __syncwarp();
                if (lane == 0) cnts[slot] = 0;
                if (c == 0) break;
                lvl++;
                if (lane == 0) loff[lvl+1] = curEnd + c;
                cur = curEnd; curEnd += c;
            }
            if (lane == 0) g_nlev[s] = lvl + 1;
        }
        __syncthreads();
        float sig = (s & 1) ? 1.0f : 0.02f;
        for (int k = tid; k < NN; k += 1024) {
            g_ord[s*NN + k] = ord[k];
            g_pp[s*NN + k]  = pp[k];
            if (k == 0) { g_w[s*NN] = 0.0f; continue; }
            int v = ord[k];
            int u = ord[pp[k]];
            int e;
            if      (u == v-1)  { int r2 = v/WW, c2 = v%WW; e = r2*(WW-1) + (c2-1); }
            else if (u == v+1)  { int r2 = v/WW, c2 = v%WW; e = r2*(WW-1) + c2; }
            else if (u == v-WW) { e = NEH + (v-WW); }
            else                { e = NEH + v; }
            g_w[s*NN + k] = expf(-(float)g_ws[s*NE + e] / sig);
        }
    }
}

// Two-pass tree DP in BFS-position space (proven R8 version). Pass 1 computes
// sigmoid(preds) inline. One block per (batch, channel).
__global__ void __launch_bounds__(256) k_filter(const float* __restrict__ preds,
                                                int t, int srcsel, int dst) {
    extern __shared__ float shf[];
    float* A = shf;               // NN  (position-indexed)
    float* S = A + NN;            // NN
    float* w = S + NN;            // NN
    int* pp    = (int*)(w + NN);  // NN
    int* ord   = pp + NN;         // NN
    int* loffs = ord + NN;        // NN+4
    int b = blockIdx.x, c = blockIdx.y;
    int s = b*2 + t;
    int nl = g_nlev[s];
    const float* s1c = g_S + (b*(CCH+1) + c)*NN;
    const float* s1n = g_S + (b*(CCH+1) + CCH)*NN;
    for (int i = threadIdx.x; i < NN; i += blockDim.x) {
        int node = g_ord[s*NN + i];
        float v;
        if (c == CCH)           v = 1.0f;
        else if (srcsel == 0)   v = 1.0f/(1.0f + expf(-preds[(b*CCH + c)*NN + node]));
        else                    v = s1c[node] / s1n[node];
        A[i]   = v;
        w[i]   = g_w[s*NN + i];
        pp[i]  = g_pp[s*NN + i];
        ord[i] = node;
    }
    for (int i = threadIdx.x; i <= nl; i += blockDim.x) loffs[i] = g_loff[s*(NN+4) + i];
    __syncthreads();
    int tid = threadIdx.x;
    // up: leaves -> root
    for (int d = nl - 1; d >= 1; d--) {
        int s0 = loffs[d], cnt2 = loffs[d+1] - s0;
        if (cnt2 <= 32) {
            if (tid < 32) {
                if (tid < cnt2) {
                    int k = s0 + tid;
                    atomicAdd(&A[pp[k]], w[k]*A[k]);
                }
                __syncwarp();
            }
        } else {
            __syncthreads();
            for (int k = s0 + tid; k < s0 + cnt2; k += blockDim.x)
                atomicAdd(&A[pp[k]], w[k]*A[k]);
            __syncthreads();
        }
    }
    __syncthreads();
    if (tid == 0) S[0] = A[0];
    __syncthreads();
    // down: root -> leaves
    for (int d = 1; d < nl; d++) {
        int s0 = loffs[d], cnt2 = loffs[d+1] - s0;
        if (cnt2 <= 32) {
            if (tid < 32) {
                if (tid < cnt2) {
                    int k = s0 + tid;
                    float wv = w[k], av = A[k];
                    S[k] = av + wv*(S[pp[k]] - wv*av);
                }
                __syncwarp();
            }
        } else {
            __syncthreads();
            for (int k = s0 + tid; k < s0 + cnt2; k += blockDim.x) {
                float wv = w[k], av = A[k];
                S[k] = av + wv*(S[pp[k]] - wv*av);
            }
            __syncthreads();
        }
    }
    __syncthreads();
    float* outS = ((dst == 0) ? g_S : g_S2) + (b*(CCH+1) + c)*NN;
    for (int i = threadIdx.x; i < NN; i += blockDim.x) outS[ord[i]] = S[i];
}

__global__ void k_loss(const float* __restrict__ preds, const float* __restrict__ roi) {
    __shared__ double sl[256], sn[256];
    int idx = blockIdx.x*blockDim.x + threadIdx.x;
    double l = 0.0, n = 0.0;
    if (idx < BN*NN) {
        int b = idx / NN, i = idx - b*NN;
        int h = i / WW, w = i - h*WW;
        float r = roi[b*(2*HH)*(2*WW) + (2*h)*(2*WW) + 2*w];
        n = (double)r;
        if (r != 0.0f) {
            float nrm = g_S2[(b*(CCH+1) + CCH)*NN + i];
            double acc = 0.0;
            for (int c = 0; c < CCH; c++) {
                float pr = 1.0f/(1.0f + expf(-preds[(b*CCH + c)*NN + i]));
                float as = g_S2[(b*(CCH+1) + c)*NN + i] / nrm;
                acc += (double)fabsf(pr - as);
            }
            l = acc * (double)r;
        }
    }
    sl[threadIdx.x] = l; sn[threadIdx.x] = n;
    __syncthreads();
    for (int o = 128; o; o >>= 1) {
        if (threadIdx.x < o) { sl[threadIdx.x] += sl[threadIdx.x+o]; sn[threadIdx.x] += sn[threadIdx.x+o]; }
        __syncthreads();
    }
    if (threadIdx.x == 0) { atomicAdd(&g_acc[0], sl[0]); atomicAdd(&g_acc[1], sn[0]); }
}

__global__ void k_fin(float* out) {
    if (threadIdx.x == 0)
        out[0] = (g_acc[1] > 0.0) ? (float)(g_acc[0]/g_acc[1]) : 0.0f;
}

// ---------------- launch ----------------
extern "C" void kernel_launch(void* const* d_in, const int* in_sizes, int n_in,
                              void* d_out, int out_size) {
    const float* preds = (const float*)d_in[0];
    const float* lf    = (const float*)d_in[1];
    const float* hf    = (const float*)d_in[2];
    const float* roi   = (const float*)d_in[3];
    float* out = (float*)d_out;

    const int smem_mstbfs = NN*4*4 + 2*NN*4 + 256;   // 221440 (bfs layout is larger)
    const int smem_filter = 5*NN*4 + (NN+4)*4;       // 221200
    cudaFuncSetAttribute(k_mstbfs, cudaFuncAttributeMaxDynamicSharedMemorySize, smem_mstbfs);
    cudaFuncSetAttribute(k_filter, cudaFuncAttributeMaxDynamicSharedMemorySize, smem_filter);

    dim3 g1(BN, CCH+1);
    k_ew_high<<<(BN*NCHUNK*NE + 255)/256, 256>>>(hf);            // 0
    k_ew_red <<<(BN*NE + 255)/256, 256>>>(lf);                   // 1
    k_mstbfs <<<NTREE, 1024, smem_mstbfs>>>();                   // 2
    k_filter <<<g1, 256, smem_filter>>>(preds, 0, 0, 0);         // 3  <- profiled slot
    k_filter <<<g1, 256, smem_filter>>>(preds, 1, 1, 1);         // 4
    k_loss   <<<(BN*NN + 255)/256, 256>>>(preds, roi);           // 5
    k_fin    <<<1, 32>>>(out);                                   // 6
}

// round 14
// speedup vs baseline: 1.2984x; 1.0388x over previous
#include <cuda_runtime.h>
#include <math.h>

#define BN 4
#define CCH 21
#define HH 96
#define WW 96
#define NN (HH*WW)          // 9216
#define NEH (HH*(WW-1))     // 9120
#define NEV ((HH-1)*WW)     // 9120
#define NE  (NEH+NEV)       // 18240
#define NTREE 8             // s = b*2 + t, t=0 low, t=1 high
#define NCHUNK 32
#define CHSZ  16            // 512 / NCHUNK
#define ROOT  (48*WW + 48)  // center root (two-pass filter is root-invariant)
#define LOFFC 1664          // smem level-offset cache entries

// ---------------- scratch ----------------
__device__ double g_ws[NTREE*NE];
__device__ unsigned long long g_key[NTREE*NE];
__device__ double g_part[BN*NCHUNK*NE];
__device__ int    g_adj[NTREE*NN*4];
__device__ int    g_ord[NTREE*NN];     // node at BFS position
__device__ int    g_pp[NTREE*NN];      // parent BFS position
__device__ int    g_loff[NTREE*(NN+4)];
__device__ int    g_nlev[NTREE];
__device__ float  g_w[NTREE*NN];       // weight, BFS-position indexed
__device__ float  g_S[BN*(CCH+1)*NN];
__device__ float  g_S2[BN*(CCH+1)*NN];
__device__ double g_acc[2];

__device__ __forceinline__ void edge_nodes(int e, int &a, int &b) {
    if (e < NEH) { int r = e / (WW-1); int c = e - r*(WW-1); a = r*WW + c; b = a + 1; }
    else         { a = e - NEH; b = a + WW; }
}

__device__ __forceinline__ unsigned long long pack_key(double w, int e) {
    unsigned long long kb = (unsigned long long)__double_as_longlong(w);
    return (kb & ~32767ull) | (unsigned long long)e;
}

__device__ __forceinline__ void two_sum(float a, float b, float &s, float &e) {
    s = __fadd_rn(a, b);
    float bp = __fsub_rn(s, a);
    e = __fadd_rn(__fsub_rn(a, __fsub_rn(s, bp)), __fsub_rn(b, bp));
}

// ---------------- kernels ----------------
__global__ void k_ew_high(const float* __restrict__ hf) {
    int idx = blockIdx.x*blockDim.x + threadIdx.x;
    if (idx >= BN*NCHUNK*NE) return;
    int b = idx / (NCHUNK*NE);
    int r = idx - b*(NCHUNK*NE);
    int ch = r / NE, e = r - ch*NE;
    int a, bb; edge_nodes(e, a, bb);
    const float* f = hf + b*512*NN + ch*CHSZ*NN;
    float sh = 0.0f, sl = 0.0f;
    #pragma unroll
    for (int c = 0; c < CHSZ; c++) {
        float av = f[c*NN+a], bv = f[c*NN+bb];
        float dh, dl; two_sum(av, -bv, dh, dl);
        float p  = __fmul_rn(dh, dh);
        float pe = __fmaf_rn(dh, dh, -p);
        pe = __fmaf_rn(__fmul_rn(2.0f, dh), dl, pe);
        float t, er; two_sum(sh, p, t, er);
        sl = __fadd_rn(sl, __fadd_rn(er, pe));
        sh = t;
    }
    g_part[(b*NCHUNK + ch)*NE + e] = (double)sh + (double)sl;
}

__global__ void k_ew_red(const float* __restrict__ lf) {
    int idx = blockIdx.x*blockDim.x + threadIdx.x;
    if (idx < 2) g_acc[idx] = 0.0;
    if (idx >= BN*NE) return;
    int b = idx / NE, e = idx - b*NE;
    int a, bb; edge_nodes(e, a, bb);
    const float* f = lf + b*3*NN;
    double accl = 0.0;
    #pragma unroll
    for (int c = 0; c < 3; c++) {
        double d = (double)f[c*NN+a] - (double)f[c*NN+bb];
        accl += d*d;
    }
    g_ws[(b*2)*NE + e] = accl;
    g_key[(b*2)*NE + e] = pack_key(accl, e);
    double acc = 0.0;
    #pragma unroll 8
    for (int ch = 0; ch < NCHUNK; ch++) acc += g_part[(b*NCHUNK + ch)*NE + e];
    g_ws[(b*2+1)*NE + e] = acc;
    g_key[(b*2+1)*NE + e] = pack_key(acc, e);
}

// Fused MST (parallel Boruvka) + BFS + weights, one block per tree.
__global__ void __launch_bounds__(1024) k_mstbfs() {
    extern __shared__ char smraw[];
    int s = blockIdx.x;
    int tid = threadIdx.x;
    // ---------- phase 1: Boruvka ----------
    {
        unsigned long long* minw = (unsigned long long*)smraw;   // NN
        int* parent = (int*)(minw + NN);                         // NN
        int* hook   = parent + NN;                               // NN
        int* deg    = hook + NN;                                 // NN
        __shared__ int total, flag;
        const unsigned long long* key = g_key + s*NE;
        int* adj = g_adj + s*NN*4;
        for (int i = tid; i < NN; i += 1024) { parent[i] = i; deg[i] = 0; }
        for (int i = tid; i < NN*4; i += 1024) adj[i] = -1;
        if (tid == 0) total = 0;
        __syncthreads();
        for (int round = 0; round < 24; round++) {
            for (int i = tid; i < NN; i += 1024) {
                minw[i] = 0xFFFFFFFFFFFFFFFFull; hook[i] = -1;
            }
            __syncthreads();
            for (int e = tid; e < NE; e += 1024) {
                int a, b; edge_nodes(e, a, b);
                int ra = parent[a], rb = parent[b];
                if (ra != rb) {
                    unsigned long long k = key[e];
                    if (k < minw[ra]) atomicMin(&minw[ra], k);
                    if (k < minw[rb]) atomicMin(&minw[rb], k);
                }
            }
            __syncthreads();
            for (int i = tid; i < NN; i += 1024) {
                unsigned long long mk = minw[i];
                if (parent[i] == i && mk != 0xFFFFFFFFFFFFFFFFull) {
                    int e = (int)(mk & 32767ull);
                    int a, b; edge_nodes(e, a, b);
                    int ra = parent[a], rb = parent[b];
                    int other = (ra == i) ? rb : ra;
                    bool mutual = (minw[other] == mk);
                    if (!mutual || i < other) {
                        int da = atomicAdd(&deg[a], 1); adj[a*4+da] = b;
                        int db = atomicAdd(&deg[b], 1); adj[b*4+db] = a;
                        atomicAdd(&total, 1);
                        hook[i] = other;
                    }
                }
            }
            __syncthreads();
            for (int i = tid; i < NN; i += 1024) {
                int t = hook[i];
                if (t >= 0) parent[i] = t;
            }
            __syncthreads();
            for (;;) {
                if (tid == 0) flag = 0;
                __syncthreads();
                for (int i = tid; i < NN; i += 1024) {
                    int p = parent[i], gp = parent[p];
                    if (p != gp) { parent[i] = gp; flag = 1; }
                }
                __syncthreads();
                int f = flag;
                __syncthreads();
                if (!f) break;
            }
            if (total >= NN-1) break;
        }
    }
    __syncthreads();
    // ---------- phase 2: single-warp BFS + weights ----------
    {
        int* adj_s = (int*)smraw;   // NN*4
        int* ord   = adj_s + NN*4;  // NN
        int* pp    = ord + NN;      // NN
        int* cnts  = pp + NN;       // 64 rotating counters
        const int* adj = g_adj + s*NN*4;
        int* loff = g_loff + s*(NN+4);
        for (int i = tid; i < NN*4; i += 1024) adj_s[i] = adj[i];
        for (int i = tid; i < 64; i += 1024) cnts[i] = 0;
        if (tid == 0) { ord[0] = ROOT; pp[0] = 0; loff[0] = 0; loff[1] = 1; }
        __syncthreads();
        if (tid < 32) {
            int lane = tid;
            int cur = 0, curEnd = 1, lvl = 0;
            for (;;) {
                int slot = lvl & 63;
                for (int q = cur + lane; q < curEnd; q += 32) {
                    int u = ord[q];
                    int pu = (q == 0) ? -1 : ord[pp[q]];
                    #pragma unroll
                    for (int j = 0; j < 4; j++) {
                        int v = adj_s[u*4 + j];
                        if (v >= 0 && v != pu) {
                            int pos = atomicAdd(&cnts[slot], 1);
                            ord[curEnd + pos] = v;
                            pp[curEnd + pos] = q;
                        }
                    }
                }
                __syncwarp();
                int c = cnts[slot];
                __syncwarp();
                if (lane == 0) cnts[slot] = 0;
                if (c == 0) break;
                lvl++;
                if (lane == 0) loff[lvl+1] = curEnd + c;
                cur = curEnd; curEnd += c;
            }
            if (lane == 0) g_nlev[s] = lvl + 1;
        }
        __syncthreads();
        float sig = (s & 1) ? 1.0f : 0.02f;
        for (int k = tid; k < NN; k += 1024) {
            g_ord[s*NN + k] = ord[k];
            g_pp[s*NN + k]  = pp[k];
            if (k == 0) { g_w[s*NN] = 0.0f; continue; }
            int v = ord[k];
            int u = ord[pp[k]];
            int e;
            if      (u == v-1)  { int r2 = v/WW, c2 = v%WW; e = r2*(WW-1) + (c2-1); }
            else if (u == v+1)  { int r2 = v/WW, c2 = v%WW; e = r2*(WW-1) + c2; }
            else if (u == v-WW) { e = NEH + (v-WW); }
            else                { e = NEH + v; }
            g_w[s*NN + k] = expf(-(float)g_ws[s*NE + e] / sig);
        }
    }
}

// Two-pass tree DP in BFS-position space. UP: proven level-sync walk.
// DOWN: parallel pointer doubling on S[v] = a_v + p_v*S[par]
//   (a_v = A'_v(1-w^2), p_v = w; root has w=0, pp=0 -> self-consistent),
// converging in ceil(log2(depth))+1 block-wide rounds (~10 us vs ~120 us).
// One block per (batch, channel). Pass 1 computes sigmoid(preds) inline.
__global__ void __launch_bounds__(256) k_filter(const float* __restrict__ preds,
                                                int t, int srcsel, int dst) {
    extern __shared__ float shf[];
    float* A  = shf;                 // NN
    float* w  = A + NN;              // NN
    int*   pp = (int*)(w + NN);      // NN
    float* A2 = (float*)(pp + NN);   // NN (doubling double-buffer)
    float* w2 = A2 + NN;             // NN
    int*   pp2= (int*)(w2 + NN);     // NN
    int* loffs= pp2 + NN;            // LOFFC
    int b = blockIdx.x, c = blockIdx.y;
    int s = b*2 + t;
    int nl = g_nlev[s];
    const float* s1c = g_S + (b*(CCH+1) + c)*NN;
    const float* s1n = g_S + (b*(CCH+1) + CCH)*NN;
    const int* ordg = g_ord + s*NN;
    for (int i = threadIdx.x; i < NN; i += blockDim.x) {
        int node = ordg[i];
        float v;
        if (c == CCH)           v = 1.0f;
        else if (srcsel == 0)   v = 1.0f/(1.0f + expf(-preds[(b*CCH + c)*NN + node]));
        else                    v = s1c[node] / s1n[node];
        A[i]  = v;
        w[i]  = g_w[s*NN + i];
        pp[i] = g_pp[s*NN + i];
    }
    bool useSm = (nl + 1 <= LOFFC);
    if (useSm)
        for (int i = threadIdx.x; i <= nl; i += blockDim.x) loffs[i] = g_loff[s*(NN+4) + i];
    const int* lof = useSm ? loffs : (g_loff + s*(NN+4));
    __syncthreads();
    int tid = threadIdx.x;
    // ---- UP: leaves -> root (level-sync, proven) ----
    for (int d = nl - 1; d >= 1; d--) {
        int s0 = lof[d], cnt2 = lof[d+1] - s0;
        if (cnt2 <= 32) {
            if (tid < 32) {
                if (tid < cnt2) {
                    int k = s0 + tid;
                    atomicAdd(&A[pp[k]], w[k]*A[k]);
                }
                __syncwarp();
            }
        } else {
            __syncthreads();
            for (int k = s0 + tid; k < s0 + cnt2; k += blockDim.x)
                atomicAdd(&A[pp[k]], w[k]*A[k]);
            __syncthreads();
        }
    }
    __syncthreads();
    // ---- DOWN: pointer doubling ----
    // transform in place: a = A'(1 - w^2); p = w; anc = pp. Root: w=0, pp=0.
    for (int k = tid; k < NN; k += 256) {
        float wv = w[k];
        A[k] = A[k]*(1.0f - wv*wv);
    }
    __syncthreads();
    int rounds = 1;
    while ((1 << rounds) < nl) rounds++;
    rounds++;
    float *a0 = A, *p0 = w, *a1 = A2, *p1 = w2;
    int *n0 = pp, *n1 = pp2;
    for (int r = 0; r < rounds; r++) {
        for (int k = tid; k < NN; k += 256) {
            int an = n0[k];
            float pk = p0[k];
            a1[k] = __fmaf_rn(pk, a0[an], a0[k]);
            p1[k] = pk * p0[an];
            n1[k] = n0[an];
        }
        __syncthreads();
        float* tf;
        int* ti;
        tf = a0; a0 = a1; a1 = tf;
        tf = p0; p0 = p1; p1 = tf;
        ti = n0; n0 = n1; n1 = ti;
    }
    // result S[k] = a0[k]
    float* outS = ((dst == 0) ? g_S : g_S2) + (b*(CCH+1) + c)*NN;
    for (int i = tid; i < NN; i += 256) outS[ordg[i]] = a0[i];
}

__global__ void k_loss(const float* __restrict__ preds, const float* __restrict__ roi) {
    __shared__ double sl[256], sn[256];
    int idx = blockIdx.x*blockDim.x + threadIdx.x;
    double l = 0.0, n = 0.0;
    if (idx < BN*NN) {
        int b = idx / NN, i = idx - b*NN;
        int h = i / WW, w = i - h*WW;
        float r = roi[b*(2*HH)*(2*WW) + (2*h)*(2*WW) + 2*w];
        n = (double)r;
        if (r != 0.0f) {
            float nrm = g_S2[(b*(CCH+1) + CCH)*NN + i];
            double acc = 0.0;
            for (int c = 0; c < CCH; c++) {
                float pr = 1.0f/(1.0f + expf(-preds[(b*CCH + c)*NN + i]));
                float as = g_S2[(b*(CCH+1) + c)*NN + i] / nrm;
                acc += (double)fabsf(pr - as);
            }
            l = acc * (double)r;
        }
    }
    sl[threadIdx.x] = l; sn[threadIdx.x] = n;
    __syncthreads();
    for (int o = 128; o; o >>= 1) {
        if (threadIdx.x < o) { sl[threadIdx.x] += sl[threadIdx.x+o]; sn[threadIdx.x] += sn[threadIdx.x+o]; }
        __syncthreads();
    }
    if (threadIdx.x == 0) { atomicAdd(&g_acc[0], sl[0]); atomicAdd(&g_acc[1], sn[0]); }
}

__global__ void k_fin(float* out) {
    if (threadIdx.x == 0)
        out[0] = (g_acc[1] > 0.0) ? (float)(g_acc[0]/g_acc[1]) : 0.0f;
}

// ---------------- launch ----------------
extern "C" void kernel_launch(void* const* d_in, const int* in_sizes, int n_in,
                              void* d_out, int out_size) {
    const float* preds = (const float*)d_in[0];
    const float* lf    = (const float*)d_in[1];
    const float* hf    = (const float*)d_in[2];
    const float* roi   = (const float*)d_in[3];
    float* out = (float*)d_out;

    const int smem_mstbfs = NN*4*4 + 2*NN*4 + 256;    // 221440
    const int smem_filter = 6*NN*4 + LOFFC*4;          // 227840
    cudaFuncSetAttribute(k_mstbfs, cudaFuncAttributeMaxDynamicSharedMemorySize, smem_mstbfs);
    cudaFuncSetAttribute(k_filter, cudaFuncAttributeMaxDynamicSharedMemorySize, smem_filter);

    dim3 g1(BN, CCH+1);
    k_ew_high<<<(BN*NCHUNK*NE + 255)/256, 256>>>(hf);            // 0
    k_ew_red <<<(BN*NE + 255)/256, 256>>>(lf);                   // 1
    k_mstbfs <<<NTREE, 1024, smem_mstbfs>>>();                   // 2
    k_filter <<<g1, 256, smem_filter>>>(preds, 0, 0, 0);         // 3  <- profiled slot
    k_filter <<<g1, 256, smem_filter>>>(preds, 1, 1, 1);         // 4
    k_loss   <<<(BN*NN + 255)/256, 256>>>(preds, roi);           // 5
    k_fin    <<<1, 32>>>(out);                                   // 6
}